// round 1
// baseline (speedup 1.0000x reference)
#include <cuda_runtime.h>

// PhysicsAttention: N=64, C=128, T=256, V=25, O=128
// out[n,o,t,v] = softmax_w( (q_v·k_w)/sqrt(O) + bias[v,w] ) @ v_w
// Restructured: scores ~ x_v^T M x_w + u·x_w (+ row-consts dropped by softmax)
//   M = Wq^T Wk / sqrt(O),  u = Wk^T bq / sqrt(O)   (precomputed once per launch)

#define TT 256
#define VV 25
#define CC 128
#define OO 128

__device__ float g_M[128 * 128];    // M[c][c'] , c' contiguous
__device__ float g_wvT[128 * 128];  // wv^T[c][o], o contiguous
__device__ float g_u[128];
__device__ float g_bias[25 * 26];   // bias[v][w], row stride 26

// ---------------- packed f32x2 helpers ----------------
__device__ __forceinline__ unsigned long long pk2(float a, float b) {
    unsigned long long r;
    asm("mov.b64 %0, {%1, %2};" : "=l"(r) : "f"(a), "f"(b));
    return r;
}
__device__ __forceinline__ void upk2(unsigned long long x, float& a, float& b) {
    asm("mov.b64 {%0, %1}, %2;" : "=f"(a), "=f"(b) : "l"(x));
}
__device__ __forceinline__ unsigned long long fma2(unsigned long long a,
                                                   unsigned long long b,
                                                   unsigned long long c) {
    unsigned long long d;
    asm("fma.rn.f32x2 %0, %1, %2, %3;" : "=l"(d) : "l"(a), "l"(b), "l"(c));
    return d;
}

// ---------------- precompute: M, u, wv^T, bias table ----------------
__global__ void precompute_kernel(const float* __restrict__ wq,
                                  const float* __restrict__ bq,
                                  const float* __restrict__ wk,
                                  const float* __restrict__ wv,
                                  const float* __restrict__ bias_emb,
                                  const int* __restrict__ hop) {
    const float inv = 0.088388347648318447f;  // 1/sqrt(128)
    int b = blockIdx.x, t = threadIdx.x;
    if (b < 128) {
        float m = 0.f;
#pragma unroll 8
        for (int o = 0; o < 128; o++)
            m += wq[o * 128 + b] * wk[o * 128 + t];
        g_M[b * 128 + t] = m * inv;
        g_wvT[b * 128 + t] = wv[t * 128 + b];
    } else if (b == 128) {
        float uu = 0.f;
#pragma unroll 8
        for (int o = 0; o < 128; o++)
            uu += bq[o] * wk[o * 128 + t];
        g_u[t] = uu * inv;
    } else {  // b == 129
        for (int i = t; i < 625; i += 128) {
            int v = i / 25, w = i - v * 25;
            g_bias[v * 26 + w] = bias_emb[hop[i]];  // bias_emb[hop][0]
        }
    }
}

// ---------------- fused per-(n,t) attention tile ----------------
__global__ __launch_bounds__(256) void attn_kernel(const float* __restrict__ x,
                                                   const float* __restrict__ bv,
                                                   float* __restrict__ out) {
    __shared__ float xs[128 * 26];  // x[c][v], v contiguous, col 25 zero-padded
    __shared__ float Gs[25 * 132];  // G'[v][c'] (reused later as outs[v][o], stride 129)
    __shared__ float Vs[25 * 128];  // V[v][o], o contiguous
    __shared__ float sc[25 * 26];   // scores
    __shared__ float at[25 * 26];   // attn^T[w][v], v contiguous

    const int tid = threadIdx.x;
    const int bid = blockIdx.x;
    const int n = bid >> 8;
    const int t = bid & 255;
    const long xbase = (long)n * (CC * TT * VV) + (long)t * VV;

    // ---- phase 1: load x tile (coalesced 25-float runs) ----
    for (int idx = tid; idx < 128 * 25; idx += 256) {
        int c = idx / 25;
        int v = idx - c * 25;
        xs[c * 26 + v] = x[xbase + (long)c * (TT * VV) + v];
    }
    for (int c = tid; c < 128; c += 256) xs[c * 26 + 25] = 0.f;
    __syncthreads();

    const int o = tid & 127;
    const int g = tid >> 7;
    const int pbase = g * 6;  // g=0: v-pairs 0..6, g=1: pairs 6..12 (pair 6 duplicated, benign)

    // ---- phase 2: V = x^T wv^T + bv  and  G' = x^T M + u   (f32x2 over v-pairs) ----
    unsigned long long accV[7], accG[7];
    {
        float bvo = __ldg(bv + o);
        float uo = g_u[o];
        unsigned long long bv2 = pk2(bvo, bvo), u2 = pk2(uo, uo);
#pragma unroll
        for (int p = 0; p < 7; p++) { accV[p] = bv2; accG[p] = u2; }
#pragma unroll 4
        for (int c = 0; c < 128; c++) {
            float wv_ = g_wvT[c * 128 + o];
            float m_ = g_M[c * 128 + o];
            unsigned long long wv2 = pk2(wv_, wv_);
            unsigned long long m2 = pk2(m_, m_);
            const unsigned long long* xr =
                (const unsigned long long*)(xs + c * 26) + pbase;
#pragma unroll
            for (int p = 0; p < 7; p++) {
                unsigned long long x2 = xr[p];
                accV[p] = fma2(x2, wv2, accV[p]);
                accG[p] = fma2(x2, m2, accG[p]);
            }
        }
    }
#pragma unroll
    for (int p = 0; p < 7; p++) {
        int v0 = 2 * (pbase + p);
        float a, b;
        upk2(accV[p], a, b);
        Vs[v0 * 128 + o] = a;
        if (v0 + 1 < 25) Vs[(v0 + 1) * 128 + o] = b;
        upk2(accG[p], a, b);
        Gs[v0 * 132 + o] = a;
        if (v0 + 1 < 25) Gs[(v0 + 1) * 132 + o] = b;
    }
    __syncthreads();

    // ---- phase 3: S[v][w] = sum_c' G'[v][c'] * x[c'][w]  (+bias) ----
    for (int W = tid; W < 325; W += 256) {
        int wp = W / 25;       // w-pair 0..12
        int v = W - wp * 25;   // 0..24
        unsigned long long acc = 0ULL;
        const float* gr = Gs + v * 132;
#pragma unroll 4
        for (int c4 = 0; c4 < 128; c4 += 4) {
            float4 g4 = *(const float4*)(gr + c4);
            acc = fma2(pk2(g4.x, g4.x),
                       *(const unsigned long long*)(xs + (c4 + 0) * 26 + 2 * wp), acc);
            acc = fma2(pk2(g4.y, g4.y),
                       *(const unsigned long long*)(xs + (c4 + 1) * 26 + 2 * wp), acc);
            acc = fma2(pk2(g4.z, g4.z),
                       *(const unsigned long long*)(xs + (c4 + 2) * 26 + 2 * wp), acc);
            acc = fma2(pk2(g4.w, g4.w),
                       *(const unsigned long long*)(xs + (c4 + 3) * 26 + 2 * wp), acc);
        }
        float s0, s1;
        upk2(acc, s0, s1);
        int w0 = 2 * wp;
        sc[v * 26 + w0] = s0 + g_bias[v * 26 + w0];
        if (w0 + 1 < 25) sc[v * 26 + w0 + 1] = s1 + g_bias[v * 26 + w0 + 1];
    }
    __syncthreads();

    // ---- phase 4: softmax rows, store transposed attn^T[w][v] ----
    {
        int lane = tid & 31, wid = tid >> 5;
        for (int v = wid; v < 25; v += 8) {
            float sv = (lane < 25) ? sc[v * 26 + lane] : -1e30f;
            float m = sv;
#pragma unroll
            for (int d = 16; d; d >>= 1)
                m = fmaxf(m, __shfl_xor_sync(0xffffffffu, m, d));
            float e = (lane < 25) ? __expf(sv - m) : 0.f;
            float s = e;
#pragma unroll
            for (int d = 16; d; d >>= 1) s += __shfl_xor_sync(0xffffffffu, s, d);
            float a = e * __fdividef(1.f, s);
            if (lane < 25) at[lane * 26 + v] = a;
        }
    }
    __syncthreads();

    // ---- phase 5: out[v][o] = sum_w attn[v][w] * V[w][o] ----
    unsigned long long accO[7];
#pragma unroll
    for (int p = 0; p < 7; p++) accO[p] = 0ULL;
#pragma unroll 1
    for (int w = 0; w < 25; w++) {
        float vv = Vs[w * 128 + o];
        unsigned long long vv2 = pk2(vv, vv);
        const unsigned long long* ar =
            (const unsigned long long*)(at + w * 26) + pbase;
#pragma unroll
        for (int p = 0; p < 7; p++) accO[p] = fma2(ar[p], vv2, accO[p]);
    }

    float* outs = Gs;  // reuse, stride 129 (conflict-free transpose read)
#pragma unroll
    for (int p = 0; p < 7; p++) {
        int v0 = 2 * (pbase + p);
        float a, b;
        upk2(accO[p], a, b);
        outs[v0 * 129 + o] = a;
        if (v0 + 1 < 25) outs[(v0 + 1) * 129 + o] = b;
    }
    __syncthreads();

    // ---- phase 6: coalesced store out[n][o][t][v] ----
    const long obase = (long)n * (OO * TT * VV) + (long)t * VV;
    for (int idx = tid; idx < 128 * 25; idx += 256) {
        int oo = idx / 25;
        int v = idx - oo * 25;
        out[obase + (long)oo * (TT * VV) + v] = outs[v * 129 + oo];
    }
}

extern "C" void kernel_launch(void* const* d_in, const int* in_sizes, int n_in,
                              void* d_out, int out_size) {
    const float* x = (const float*)d_in[0];
    const float* wq = (const float*)d_in[1];
    const float* bq = (const float*)d_in[2];
    const float* wk = (const float*)d_in[3];
    // d_in[4] = bk: softmax-invariant (row-constant), unused
    const float* wv = (const float*)d_in[5];
    const float* bv = (const float*)d_in[6];
    const float* be = (const float*)d_in[7];
    const int* hop = (const int*)d_in[8];

    precompute_kernel<<<130, 128>>>(wq, bq, wk, wv, be, hop);
    attn_kernel<<<64 * 256, 256>>>(x, bv, (float*)d_out);
}

// round 2
// speedup vs baseline: 1.0024x; 1.0024x over previous
#include <cuda_runtime.h>

// PhysicsAttention: N=64, C=128, T=256, V=25, O=128
// out[n,o,t,v] = softmax_w( (q_v·k_w)/sqrt(O) + bias[v,w] ) @ v_w
// Restructured: scores ~ x_v^T M x_w + u·x_w (+ row-consts dropped by softmax)
//   M = Wq^T Wk / sqrt(O),  u = Wk^T bq / sqrt(O)   (precomputed once per launch)

#define TT 256
#define VV 25
#define CC 128
#define OO 128

__device__ float g_M[128 * 128];    // M[c][c'] , c' contiguous
__device__ float g_wvT[128 * 128];  // wv^T[c][o], o contiguous
__device__ float g_u[128];
__device__ float g_bias[25 * 26];   // bias[v][w], row stride 26

// ---------------- packed f32x2 helpers ----------------
__device__ __forceinline__ unsigned long long pk2(float a, float b) {
    unsigned long long r;
    asm("mov.b64 %0, {%1, %2};" : "=l"(r) : "f"(a), "f"(b));
    return r;
}
__device__ __forceinline__ void upk2(unsigned long long x, float& a, float& b) {
    asm("mov.b64 {%0, %1}, %2;" : "=f"(a), "=f"(b) : "l"(x));
}
__device__ __forceinline__ unsigned long long fma2(unsigned long long a,
                                                   unsigned long long b,
                                                   unsigned long long c) {
    unsigned long long d;
    asm("fma.rn.f32x2 %0, %1, %2, %3;" : "=l"(d) : "l"(a), "l"(b), "l"(c));
    return d;
}

// ---------------- precompute: M, u, wv^T, bias table ----------------
__global__ void precompute_kernel(const float* __restrict__ wq,
                                  const float* __restrict__ bq,
                                  const float* __restrict__ wk,
                                  const float* __restrict__ wv,
                                  const float* __restrict__ bias_emb,
                                  const int* __restrict__ hop) {
    const float inv = 0.088388347648318447f;  // 1/sqrt(128)
    int b = blockIdx.x, t = threadIdx.x;
    if (b < 128) {
        float m = 0.f;
#pragma unroll 8
        for (int o = 0; o < 128; o++)
            m += wq[o * 128 + b] * wk[o * 128 + t];
        g_M[b * 128 + t] = m * inv;
        g_wvT[b * 128 + t] = wv[t * 128 + b];
    } else if (b == 128) {
        float uu = 0.f;
#pragma unroll 8
        for (int o = 0; o < 128; o++)
            uu += bq[o] * wk[o * 128 + t];
        g_u[t] = uu * inv;
    } else {  // b == 129
        for (int i = t; i < 625; i += 128) {
            int v = i / 25, w = i - v * 25;
            g_bias[v * 26 + w] = bias_emb[hop[i]];  // bias_emb[hop][0]
        }
    }
}

// ---------------- fused per-(n,t) attention tile ----------------
__global__ __launch_bounds__(256) void attn_kernel(const float* __restrict__ x,
                                                   const float* __restrict__ bv,
                                                   float* __restrict__ out) {
    __shared__ float xs[128 * 26];  // x[c][v], v contiguous, col 25 zero-padded
    __shared__ float Gs[25 * 132];  // G'[v][c'] (reused later as outs[v][o], stride 129)
    __shared__ float Vs[25 * 128];  // V[v][o], o contiguous
    __shared__ float sc[25 * 26];   // scores
    __shared__ float at[25 * 26];   // attn^T[w][v], v contiguous

    const int tid = threadIdx.x;
    const int bid = blockIdx.x;
    const int n = bid >> 8;
    const int t = bid & 255;
    const long xbase = (long)n * (CC * TT * VV) + (long)t * VV;

    // ---- phase 1: load x tile (coalesced 25-float runs) ----
    for (int idx = tid; idx < 128 * 25; idx += 256) {
        int c = idx / 25;
        int v = idx - c * 25;
        xs[c * 26 + v] = x[xbase + (long)c * (TT * VV) + v];
    }
    for (int c = tid; c < 128; c += 256) xs[c * 26 + 25] = 0.f;
    __syncthreads();

    const int o = tid & 127;
    const int g = tid >> 7;
    const int pbase = g * 6;  // g=0: v-pairs 0..6, g=1: pairs 6..12 (pair 6 duplicated, benign)

    // ---- phase 2: V = x^T wv^T + bv  and  G' = x^T M + u   (f32x2 over v-pairs) ----
    unsigned long long accV[7], accG[7];
    {
        float bvo = __ldg(bv + o);
        float uo = g_u[o];
        unsigned long long bv2 = pk2(bvo, bvo), u2 = pk2(uo, uo);
#pragma unroll
        for (int p = 0; p < 7; p++) { accV[p] = bv2; accG[p] = u2; }
#pragma unroll 4
        for (int c = 0; c < 128; c++) {
            float wv_ = g_wvT[c * 128 + o];
            float m_ = g_M[c * 128 + o];
            unsigned long long wv2 = pk2(wv_, wv_);
            unsigned long long m2 = pk2(m_, m_);
            const unsigned long long* xr =
                (const unsigned long long*)(xs + c * 26) + pbase;
#pragma unroll
            for (int p = 0; p < 7; p++) {
                unsigned long long x2 = xr[p];
                accV[p] = fma2(x2, wv2, accV[p]);
                accG[p] = fma2(x2, m2, accG[p]);
            }
        }
    }
#pragma unroll
    for (int p = 0; p < 7; p++) {
        int v0 = 2 * (pbase + p);
        float a, b;
        upk2(accV[p], a, b);
        Vs[v0 * 128 + o] = a;
        if (v0 + 1 < 25) Vs[(v0 + 1) * 128 + o] = b;
        upk2(accG[p], a, b);
        Gs[v0 * 132 + o] = a;
        if (v0 + 1 < 25) Gs[(v0 + 1) * 132 + o] = b;
    }
    __syncthreads();

    // ---- phase 3: S[v][w] = sum_c' G'[v][c'] * x[c'][w]  (+bias) ----
    for (int W = tid; W < 325; W += 256) {
        int wp = W / 25;       // w-pair 0..12
        int v = W - wp * 25;   // 0..24
        unsigned long long acc = 0ULL;
        const float* gr = Gs + v * 132;
#pragma unroll 4
        for (int c4 = 0; c4 < 128; c4 += 4) {
            float4 g4 = *(const float4*)(gr + c4);
            acc = fma2(pk2(g4.x, g4.x),
                       *(const unsigned long long*)(xs + (c4 + 0) * 26 + 2 * wp), acc);
            acc = fma2(pk2(g4.y, g4.y),
                       *(const unsigned long long*)(xs + (c4 + 1) * 26 + 2 * wp), acc);
            acc = fma2(pk2(g4.z, g4.z),
                       *(const unsigned long long*)(xs + (c4 + 2) * 26 + 2 * wp), acc);
            acc = fma2(pk2(g4.w, g4.w),
                       *(const unsigned long long*)(xs + (c4 + 3) * 26 + 2 * wp), acc);
        }
        float s0, s1;
        upk2(acc, s0, s1);
        int w0 = 2 * wp;
        sc[v * 26 + w0] = s0 + g_bias[v * 26 + w0];
        if (w0 + 1 < 25) sc[v * 26 + w0 + 1] = s1 + g_bias[v * 26 + w0 + 1];
    }
    __syncthreads();

    // ---- phase 4: softmax rows, store transposed attn^T[w][v] ----
    {
        int lane = tid & 31, wid = tid >> 5;
        for (int v = wid; v < 25; v += 8) {
            float sv = (lane < 25) ? sc[v * 26 + lane] : -1e30f;
            float m = sv;
#pragma unroll
            for (int d = 16; d; d >>= 1)
                m = fmaxf(m, __shfl_xor_sync(0xffffffffu, m, d));
            float e = (lane < 25) ? __expf(sv - m) : 0.f;
            float s = e;
#pragma unroll
            for (int d = 16; d; d >>= 1) s += __shfl_xor_sync(0xffffffffu, s, d);
            float a = e * __fdividef(1.f, s);
            if (lane < 25) at[lane * 26 + v] = a;
        }
    }
    __syncthreads();

    // ---- phase 5: out[v][o] = sum_w attn[v][w] * V[w][o] ----
    unsigned long long accO[7];
#pragma unroll
    for (int p = 0; p < 7; p++) accO[p] = 0ULL;
#pragma unroll 1
    for (int w = 0; w < 25; w++) {
        float vv = Vs[w * 128 + o];
        unsigned long long vv2 = pk2(vv, vv);
        const unsigned long long* ar =
            (const unsigned long long*)(at + w * 26) + pbase;
#pragma unroll
        for (int p = 0; p < 7; p++) accO[p] = fma2(ar[p], vv2, accO[p]);
    }

    float* outs = Gs;  // reuse, stride 129 (conflict-free transpose read)
#pragma unroll
    for (int p = 0; p < 7; p++) {
        int v0 = 2 * (pbase + p);
        float a, b;
        upk2(accO[p], a, b);
        outs[v0 * 129 + o] = a;
        if (v0 + 1 < 25) outs[(v0 + 1) * 129 + o] = b;
    }
    __syncthreads();

    // ---- phase 6: coalesced store out[n][o][t][v] ----
    const long obase = (long)n * (OO * TT * VV) + (long)t * VV;
    for (int idx = tid; idx < 128 * 25; idx += 256) {
        int oo = idx / 25;
        int v = idx - oo * 25;
        out[obase + (long)oo * (TT * VV) + v] = outs[v * 129 + oo];
    }
}

extern "C" void kernel_launch(void* const* d_in, const int* in_sizes, int n_in,
                              void* d_out, int out_size) {
    const float* x = (const float*)d_in[0];
    const float* wq = (const float*)d_in[1];
    const float* bq = (const float*)d_in[2];
    const float* wk = (const float*)d_in[3];
    // d_in[4] = bk: softmax-invariant (row-constant), unused
    const float* wv = (const float*)d_in[5];
    const float* bv = (const float*)d_in[6];
    const float* be = (const float*)d_in[7];
    const int* hop = (const int*)d_in[8];

    precompute_kernel<<<130, 128>>>(wq, bq, wk, wv, be, hop);
    attn_kernel<<<64 * 256, 256>>>(x, bv, (float*)d_out);
}